// round 2
// baseline (speedup 1.0000x reference)
#include <cuda_runtime.h>
#include <cuda_bf16.h>
#include <cuda_fp16.h>

#define NB 8
#define NT 256   // T_en == T_de
#define ND 256
#define NU 256

// Scratch (device globals: no allocation allowed in kernel_launch)
__device__ float d_aeT[NB * NU * NT];  // aeT[b][u][e]  (transposed for coalesced e-reads)
__device__ float d_ad [NB * NT * NU];  // ad [b][t][u]

// ---------------------------------------------------------------------------
// Fused GEMM: computes both att_en (transposed store) and att_de.
//   which=0: C[e][u] = sum_d en[b][e][d] * w_en[d][u]  -> store d_aeT[b][u][e]
//   which=1: C[t][u] = sum_d de[b][t][d] * w_de[d][u]  -> store d_ad [b][t][u]
// 64x64 tile, 256 threads, 4x4 per-thread micro-tile, K-step 16.
// ---------------------------------------------------------------------------
__global__ __launch_bounds__(256) void gemm_kernel(const float* __restrict__ en,
                                                   const float* __restrict__ de,
                                                   const float* __restrict__ w_en,
                                                   const float* __restrict__ w_de)
{
    const int z     = blockIdx.z;
    const int b     = z >> 1;
    const int which = z & 1;

    const float* A  = which ? (de + b * NT * ND) : (en + b * NT * ND);  // (M=256, K=256) row-major
    const float* Bm = which ? w_de : w_en;                               // (K=256, N=256) row-major

    const int m0 = blockIdx.y * 64;
    const int n0 = blockIdx.x * 64;

    __shared__ float As[16][68];  // As[k][m], padded
    __shared__ float Bs[16][64];  // Bs[k][n]

    const int tid   = threadIdx.x;
    const int a_row = tid >> 2;          // 0..63
    const int a_k4  = (tid & 3) << 2;    // 0,4,8,12
    const int b_k   = tid >> 4;          // 0..15
    const int b_n4  = (tid & 15) << 2;   // 0..60
    const int tm    = tid >> 4;          // 0..15
    const int tn    = tid & 15;          // 0..15

    float acc[4][4];
#pragma unroll
    for (int i = 0; i < 4; i++)
#pragma unroll
        for (int j = 0; j < 4; j++) acc[i][j] = 0.f;

    for (int k0 = 0; k0 < 256; k0 += 16) {
        float4 av = *(const float4*)(A  + (m0 + a_row) * 256 + k0 + a_k4);
        float4 bv = *(const float4*)(Bm + (k0 + b_k)   * 256 + n0 + b_n4);
        __syncthreads();
        As[a_k4 + 0][a_row] = av.x;
        As[a_k4 + 1][a_row] = av.y;
        As[a_k4 + 2][a_row] = av.z;
        As[a_k4 + 3][a_row] = av.w;
        *(float4*)&Bs[b_k][b_n4] = bv;
        __syncthreads();
#pragma unroll
        for (int k = 0; k < 16; k++) {
            float4 a4 = *(const float4*)&As[k][tm << 2];
            float4 b4 = *(const float4*)&Bs[k][tn << 2];
            float ar[4] = {a4.x, a4.y, a4.z, a4.w};
            float br[4] = {b4.x, b4.y, b4.z, b4.w};
#pragma unroll
            for (int i = 0; i < 4; i++)
#pragma unroll
                for (int j = 0; j < 4; j++)
                    acc[i][j] = fmaf(ar[i], br[j], acc[i][j]);
        }
    }

    if (which == 0) {
        float* dst = d_aeT + b * NU * NT;
#pragma unroll
        for (int j = 0; j < 4; j++) {
            int u = n0 + (tn << 2) + j;
            float4 v = make_float4(acc[0][j], acc[1][j], acc[2][j], acc[3][j]);
            *(float4*)(dst + u * NT + m0 + (tm << 2)) = v;
        }
    } else {
        float* dst = d_ad + b * NT * NU;
#pragma unroll
        for (int i = 0; i < 4; i++) {
            int t = m0 + (tm << 2) + i;
            float4 v = make_float4(acc[i][0], acc[i][1], acc[i][2], acc[i][3]);
            *(float4*)(dst + t * NU + n0 + (tn << 2)) = v;
        }
    }
}

// ---------------------------------------------------------------------------
// Fused tanh-score + softmax + context kernel.
// One CTA = (b, 4 consecutive decoder rows). Thread = encoder step e (scores),
// feature d (context).
// Scores use f16x2 tanh (2 tanhs per MUFU op), fp32 accumulation.
// ---------------------------------------------------------------------------
struct __align__(16) AdPack {
    __half2 ad01;   // (ad[t0][u], ad[t1][u])
    __half2 ad23;   // (ad[t2][u], ad[t3][u])
    float   nu;
    float   pad;
};

__global__ __launch_bounds__(256) void attn_kernel(const float* __restrict__ en,
                                                   const float* __restrict__ de,
                                                   const float* __restrict__ nu,
                                                   float* __restrict__ out)
{
    const int b   = blockIdx.x >> 6;          // 8 b * 64 groups
    const int t0  = (blockIdx.x & 63) << 2;   // 4 decoder rows per CTA
    const int tid = threadIdx.x;

    __shared__ AdPack adp[256];     // 16B/u: packed ad row-pairs + nu
    __shared__ float4 alpha4[256];  // (alpha[t0..t0+3][e]) packed per e
    __shared__ float  red[8];

    {
        const float* ap = d_ad + (b * NT + t0) * NU + tid;
        AdPack p;
        p.ad01 = __floats2half2_rn(ap[0],      ap[NU]);
        p.ad23 = __floats2half2_rn(ap[2 * NU], ap[3 * NU]);
        p.nu   = nu[tid];
        p.pad  = 0.f;
        adp[tid] = p;
    }
    __syncthreads();

    // ---- scores: thread = e, loop u ----
    const float* ae = d_aeT + b * NU * NT + tid;
    float m0 = 0.f, m1 = 0.f, m2 = 0.f, m3 = 0.f;
#pragma unroll 8
    for (int u = 0; u < 256; ++u) {
        float a = ae[u << 8];                       // LDG, coalesced, L2-resident
        __half2 ah = __float2half2_rn(a);
        uint4 praw = *(const uint4*)&adp[u];        // LDS.128 broadcast
        __half2 ad01 = *(__half2*)&praw.x;
        __half2 ad23 = *(__half2*)&praw.y;
        float   w    = __uint_as_float(praw.z);
        __half2 c01 = __hadd2(ah, ad01);
        __half2 c23 = __hadd2(ah, ad23);
        unsigned t01, t23;
        asm("tanh.approx.f16x2 %0, %1;" : "=r"(t01) : "r"(*(unsigned*)&c01));
        asm("tanh.approx.f16x2 %0, %1;" : "=r"(t23) : "r"(*(unsigned*)&c23));
        float2 f01 = __half22float2(*(__half2*)&t01);
        float2 f23 = __half22float2(*(__half2*)&t23);
        m0 = fmaf(w, f01.x, m0);
        m1 = fmaf(w, f01.y, m1);
        m2 = fmaf(w, f23.x, m2);
        m3 = fmaf(w, f23.y, m3);
    }

    // ---- softmax over e for each of the 4 rows ----
    float mu[4] = {m0, m1, m2, m3};
    float al[4];
#pragma unroll
    for (int tt = 0; tt < 4; tt++) {
        float v  = mu[tt];
        float mx = v;
#pragma unroll
        for (int o = 16; o; o >>= 1) mx = fmaxf(mx, __shfl_xor_sync(0xffffffffu, mx, o));
        if ((tid & 31) == 0) red[tid >> 5] = mx;
        __syncthreads();
        mx = fmaxf(fmaxf(fmaxf(red[0], red[1]), fmaxf(red[2], red[3])),
                   fmaxf(fmaxf(red[4], red[5]), fmaxf(red[6], red[7])));
        __syncthreads();
        float ex = __expf(v - mx);
        float s  = ex;
#pragma unroll
        for (int o = 16; o; o >>= 1) s += __shfl_xor_sync(0xffffffffu, s, o);
        if ((tid & 31) == 0) red[tid >> 5] = s;
        __syncthreads();
        s = ((red[0] + red[1]) + (red[2] + red[3])) + ((red[4] + red[5]) + (red[6] + red[7]));
        __syncthreads();
        al[tt] = __fdividef(ex, s);
    }
    alpha4[tid] = make_float4(al[0], al[1], al[2], al[3]);
    __syncthreads();

    // ---- context: thread = d, loop e ----
    const float* enb = en + b * NT * ND + tid;
    const float* dep = de + (b * NT + t0) * ND + tid;
    float o0 = dep[0], o1 = dep[ND], o2 = dep[2 * ND], o3 = dep[3 * ND];
#pragma unroll 4
    for (int e = 0; e < 256; ++e) {
        float  v = enb[e << 8];
        float4 a = alpha4[e];
        o0 = fmaf(a.x, v, o0);
        o1 = fmaf(a.y, v, o1);
        o2 = fmaf(a.z, v, o2);
        o3 = fmaf(a.w, v, o3);
    }
    float* op = out + (b * NT + t0) * ND + tid;
    op[0] = o0; op[ND] = o1; op[2 * ND] = o2; op[3 * ND] = o3;
}

extern "C" void kernel_launch(void* const* d_in, const int* in_sizes, int n_in,
                              void* d_out, int out_size)
{
    const float* en   = (const float*)d_in[0];   // (8,256,256)
    const float* de   = (const float*)d_in[1];   // (8,256,256)
    const float* w_en = (const float*)d_in[2];   // (256,256)
    const float* w_de = (const float*)d_in[3];   // (256,256)
    const float* nu   = (const float*)d_in[4];   // (256,1)
    float* out = (float*)d_out;                  // (8,256,256) fp32

    dim3 gg(4, 4, 16);                // 4 n-tiles, 4 m-tiles, 8 b * 2 matrices
    gemm_kernel<<<gg, 256>>>(en, de, w_en, w_de);
    attn_kernel<<<NB * (NT / 4), 256>>>(en, de, nu, out);
}

// round 3
// speedup vs baseline: 1.0300x; 1.0300x over previous
#include <cuda_runtime.h>
#include <cuda_bf16.h>
#include <cuda_fp16.h>

#define NB 8
#define NT 256   // T_en == T_de
#define ND 256
#define NU 256

// Scratch (device globals: no allocation allowed in kernel_launch)
__device__ __half d_aeT_h[NB * NU * NT];  // aeT[b][u][e] fp16 (coalesced e-reads)
__device__ float  d_ad   [NB * NT * NU];  // ad [b][t][u] fp32
__device__ __half d_en_h [NB * NT * ND];  // en[b][e][d] fp16 copy for context phase

// ---------------------------------------------------------------------------
// en -> fp16 copy (context phase reads this; halves L2 traffic there)
// ---------------------------------------------------------------------------
__global__ __launch_bounds__(256) void prep_kernel(const float* __restrict__ en)
{
    int i = blockIdx.x * 256 + threadIdx.x;      // over 2M/4 float4s
    float4 v = ((const float4*)en)[i];
    __half2 lo = __floats2half2_rn(v.x, v.y);
    __half2 hi = __floats2half2_rn(v.z, v.w);
    uint2 o;
    o.x = *(unsigned*)&lo;
    o.y = *(unsigned*)&hi;
    ((uint2*)d_en_h)[i] = o;
}

// ---------------------------------------------------------------------------
// Fused GEMM: computes both att_en (fp16 transposed store) and att_de (fp32).
//   which=0: C[e][u] = sum_d en[b][e][d] * w_en[d][u] -> d_aeT_h[b][u][e] (half)
//   which=1: C[t][u] = sum_d de[b][t][d] * w_de[d][u] -> d_ad  [b][t][u] (float)
// ---------------------------------------------------------------------------
__global__ __launch_bounds__(256) void gemm_kernel(const float* __restrict__ en,
                                                   const float* __restrict__ de,
                                                   const float* __restrict__ w_en,
                                                   const float* __restrict__ w_de)
{
    const int z     = blockIdx.z;
    const int b     = z >> 1;
    const int which = z & 1;

    const float* A  = which ? (de + b * NT * ND) : (en + b * NT * ND);
    const float* Bm = which ? w_de : w_en;

    const int m0 = blockIdx.y * 64;
    const int n0 = blockIdx.x * 64;

    __shared__ float As[16][68];
    __shared__ float Bs[16][64];

    const int tid   = threadIdx.x;
    const int a_row = tid >> 2;
    const int a_k4  = (tid & 3) << 2;
    const int b_k   = tid >> 4;
    const int b_n4  = (tid & 15) << 2;
    const int tm    = tid >> 4;
    const int tn    = tid & 15;

    float acc[4][4];
#pragma unroll
    for (int i = 0; i < 4; i++)
#pragma unroll
        for (int j = 0; j < 4; j++) acc[i][j] = 0.f;

    for (int k0 = 0; k0 < 256; k0 += 16) {
        float4 av = *(const float4*)(A  + (m0 + a_row) * 256 + k0 + a_k4);
        float4 bv = *(const float4*)(Bm + (k0 + b_k)   * 256 + n0 + b_n4);
        __syncthreads();
        As[a_k4 + 0][a_row] = av.x;
        As[a_k4 + 1][a_row] = av.y;
        As[a_k4 + 2][a_row] = av.z;
        As[a_k4 + 3][a_row] = av.w;
        *(float4*)&Bs[b_k][b_n4] = bv;
        __syncthreads();
#pragma unroll
        for (int k = 0; k < 16; k++) {
            float4 a4 = *(const float4*)&As[k][tm << 2];
            float4 b4 = *(const float4*)&Bs[k][tn << 2];
            float ar[4] = {a4.x, a4.y, a4.z, a4.w};
            float br[4] = {b4.x, b4.y, b4.z, b4.w};
#pragma unroll
            for (int i = 0; i < 4; i++)
#pragma unroll
                for (int j = 0; j < 4; j++)
                    acc[i][j] = fmaf(ar[i], br[j], acc[i][j]);
        }
    }

    if (which == 0) {
        // C[e][u] -> aeT_h[b][u][e] fp16; per j: 4 contiguous e values (8B store)
        __half* dst = d_aeT_h + b * NU * NT;
#pragma unroll
        for (int j = 0; j < 4; j++) {
            int u = n0 + (tn << 2) + j;
            __half2 lo = __floats2half2_rn(acc[0][j], acc[1][j]);
            __half2 hi = __floats2half2_rn(acc[2][j], acc[3][j]);
            uint2 v;
            v.x = *(unsigned*)&lo;
            v.y = *(unsigned*)&hi;
            *(uint2*)(dst + u * NT + m0 + (tm << 2)) = v;
        }
    } else {
        float* dst = d_ad + b * NT * NU;
#pragma unroll
        for (int i = 0; i < 4; i++) {
            int t = m0 + (tm << 2) + i;
            float4 v = make_float4(acc[i][0], acc[i][1], acc[i][2], acc[i][3]);
            *(float4*)(dst + t * NU + n0 + (tn << 2)) = v;
        }
    }
}

// ---------------------------------------------------------------------------
// Fused tanh-score + softmax + context. One CTA = (b, 2 decoder rows).
// 1024 CTAs -> ~55 warps/SM (occupancy fix). Scores: fp16 HFMA2 accumulation
// in 16-u chunks, flushed to fp32 (cuts F2F/FFMA per u).
// ---------------------------------------------------------------------------
__global__ __launch_bounds__(256) void attn_kernel(const float* __restrict__ de,
                                                   const float* __restrict__ nu,
                                                   float* __restrict__ out)
{
    const int b   = blockIdx.x >> 7;           // 8 b * 128 groups
    const int t0  = (blockIdx.x & 127) << 1;   // 2 decoder rows per CTA
    const int tid = threadIdx.x;

    __shared__ float2 pk[256];      // {.x bits = half2(ad_t0,ad_t1), .y bits = half2(nu,nu)}
    __shared__ float2 alpha2[256];  // (alpha[t0][e], alpha[t1][e])
    __shared__ float  red[8];

    {
        const float* ap = d_ad + (b * NT + t0) * NU + tid;
        __half2 ad01 = __floats2half2_rn(ap[0], ap[NU]);
        float nv = nu[tid];
        __half2 nu2 = __float2half2_rn(nv);
        float2 p;
        p.x = *(float*)&ad01;
        p.y = *(float*)&nu2;
        pk[tid] = p;
    }
    __syncthreads();

    // ---- scores: thread = e, loop u (chunked fp16 accumulation) ----
    const __half* ae = d_aeT_h + b * NU * NT + tid;
    float m0 = 0.f, m1 = 0.f;
    for (int u0 = 0; u0 < 256; u0 += 16) {
        __half2 acc = __float2half2_rn(0.f);
#pragma unroll
        for (int k = 0; k < 16; k++) {
            int u = u0 + k;
            __half  a    = ae[u << 8];            // LDG.16, coalesced, L2-resident
            __half2 ah   = __half2half2(a);
            float2  p    = pk[u];                 // LDS.64 broadcast
            __half2 ad01 = *(__half2*)&p.x;
            __half2 nu2  = *(__half2*)&p.y;
            __half2 c    = __hadd2(ah, ad01);
            unsigned th;
            asm("tanh.approx.f16x2 %0, %1;" : "=r"(th) : "r"(*(unsigned*)&c));
            acc = __hfma2(*(__half2*)&th, nu2, acc);
        }
        float2 f = __half22float2(acc);
        m0 += f.x;
        m1 += f.y;
    }

    // ---- softmax over e for the 2 rows ----
    float mu[2] = {m0, m1};
    float al[2];
#pragma unroll
    for (int tt = 0; tt < 2; tt++) {
        float v  = mu[tt];
        float mx = v;
#pragma unroll
        for (int o = 16; o; o >>= 1) mx = fmaxf(mx, __shfl_xor_sync(0xffffffffu, mx, o));
        if ((tid & 31) == 0) red[tid >> 5] = mx;
        __syncthreads();
        mx = fmaxf(fmaxf(fmaxf(red[0], red[1]), fmaxf(red[2], red[3])),
                   fmaxf(fmaxf(red[4], red[5]), fmaxf(red[6], red[7])));
        __syncthreads();
        float ex = __expf(v - mx);
        float s  = ex;
#pragma unroll
        for (int o = 16; o; o >>= 1) s += __shfl_xor_sync(0xffffffffu, s, o);
        if ((tid & 31) == 0) red[tid >> 5] = s;
        __syncthreads();
        s = ((red[0] + red[1]) + (red[2] + red[3])) + ((red[4] + red[5]) + (red[6] + red[7]));
        __syncthreads();
        al[tt] = __fdividef(ex, s);
    }
    alpha2[tid] = make_float2(al[0], al[1]);
    __syncthreads();

    // ---- context: thread = d, loop e (en fp16, fp32 accumulation) ----
    const __half* enb = d_en_h + b * NT * ND + tid;
    const float*  dep = de + (b * NT + t0) * ND + tid;
    float o0 = dep[0], o1 = dep[ND];
#pragma unroll 8
    for (int e = 0; e < 256; ++e) {
        float  v = __half2float(enb[e << 8]);
        float2 a = alpha2[e];
        o0 = fmaf(a.x, v, o0);
        o1 = fmaf(a.y, v, o1);
    }
    float* op = out + (b * NT + t0) * ND + tid;
    op[0] = o0;
    op[ND] = o1;
}

extern "C" void kernel_launch(void* const* d_in, const int* in_sizes, int n_in,
                              void* d_out, int out_size)
{
    const float* en   = (const float*)d_in[0];   // (8,256,256)
    const float* de   = (const float*)d_in[1];   // (8,256,256)
    const float* w_en = (const float*)d_in[2];   // (256,256)
    const float* w_de = (const float*)d_in[3];   // (256,256)
    const float* nu   = (const float*)d_in[4];   // (256,1)
    float* out = (float*)d_out;                  // (8,256,256) fp32

    prep_kernel<<<NB * NT * ND / 4 / 256, 256>>>(en);
    dim3 gg(4, 4, 16);
    gemm_kernel<<<gg, 256>>>(en, de, w_en, w_de);
    attn_kernel<<<NB * (NT / 2), 256>>>(de, nu, out);
}

// round 4
// speedup vs baseline: 1.1398x; 1.1066x over previous
#include <cuda_runtime.h>
#include <cuda_bf16.h>
#include <cuda_fp16.h>

#define NB 8
#define NT 256   // T_en == T_de
#define ND 256
#define NU 256

// Scratch (device globals: no allocation allowed in kernel_launch)
__device__ __half d_aeT_h[NB * NU * NT];  // aeT[b][u][e] fp16 (e contiguous)
__device__ float  d_ad   [NB * NT * NU];  // ad [b][t][u] fp32
__device__ __half d_en_h [NB * NT * ND];  // en[b][e][d] fp16 (d contiguous)

// ---------------------------------------------------------------------------
// Fused GEMM: att_en (fp16 transposed store) and att_de (fp32).
//   which=0: C[e][u] = sum_d en[b][e][d] * w_en[d][u] -> d_aeT_h[b][u][e]
//            (+ n0==0 blocks also emit en in fp16 to d_en_h)
//   which=1: C[t][u] = sum_d de[b][t][d] * w_de[d][u] -> d_ad[b][t][u]
// ---------------------------------------------------------------------------
__global__ __launch_bounds__(256) void gemm_kernel(const float* __restrict__ en,
                                                   const float* __restrict__ de,
                                                   const float* __restrict__ w_en,
                                                   const float* __restrict__ w_de)
{
    const int z     = blockIdx.z;
    const int b     = z >> 1;
    const int which = z & 1;

    const float* A  = which ? (de + b * NT * ND) : (en + b * NT * ND);
    const float* Bm = which ? w_de : w_en;

    const int m0 = blockIdx.y * 64;
    const int n0 = blockIdx.x * 64;

    __shared__ float As[16][68];
    __shared__ float Bs[16][64];

    const int tid   = threadIdx.x;
    const int a_row = tid >> 2;
    const int a_k4  = (tid & 3) << 2;
    const int b_k   = tid >> 4;
    const int b_n4  = (tid & 15) << 2;
    const int tm    = tid >> 4;
    const int tn    = tid & 15;

    const bool emit_en = (which == 0) && (n0 == 0);

    float acc[4][4];
#pragma unroll
    for (int i = 0; i < 4; i++)
#pragma unroll
        for (int j = 0; j < 4; j++) acc[i][j] = 0.f;

    for (int k0 = 0; k0 < 256; k0 += 16) {
        float4 av = *(const float4*)(A  + (m0 + a_row) * 256 + k0 + a_k4);
        float4 bv = *(const float4*)(Bm + (k0 + b_k)   * 256 + n0 + b_n4);
        if (emit_en) {
            __half2 lo = __floats2half2_rn(av.x, av.y);
            __half2 hi = __floats2half2_rn(av.z, av.w);
            uint2 o;
            o.x = *(unsigned*)&lo;
            o.y = *(unsigned*)&hi;
            *(uint2*)(d_en_h + b * NT * ND + (m0 + a_row) * ND + k0 + a_k4) = o;
        }
        __syncthreads();
        As[a_k4 + 0][a_row] = av.x;
        As[a_k4 + 1][a_row] = av.y;
        As[a_k4 + 2][a_row] = av.z;
        As[a_k4 + 3][a_row] = av.w;
        *(float4*)&Bs[b_k][b_n4] = bv;
        __syncthreads();
#pragma unroll
        for (int k = 0; k < 16; k++) {
            float4 a4 = *(const float4*)&As[k][tm << 2];
            float4 b4 = *(const float4*)&Bs[k][tn << 2];
            float ar[4] = {a4.x, a4.y, a4.z, a4.w};
            float br[4] = {b4.x, b4.y, b4.z, b4.w};
#pragma unroll
            for (int i = 0; i < 4; i++)
#pragma unroll
                for (int j = 0; j < 4; j++)
                    acc[i][j] = fmaf(ar[i], br[j], acc[i][j]);
        }
    }

    if (which == 0) {
        __half* dst = d_aeT_h + b * NU * NT;
#pragma unroll
        for (int j = 0; j < 4; j++) {
            int u = n0 + (tn << 2) + j;
            __half2 lo = __floats2half2_rn(acc[0][j], acc[1][j]);
            __half2 hi = __floats2half2_rn(acc[2][j], acc[3][j]);
            uint2 v;
            v.x = *(unsigned*)&lo;
            v.y = *(unsigned*)&hi;
            *(uint2*)(dst + u * NT + m0 + (tm << 2)) = v;
        }
    } else {
        float* dst = d_ad + b * NT * NU;
#pragma unroll
        for (int i = 0; i < 4; i++) {
            int t = m0 + (tm << 2) + i;
            float4 v = make_float4(acc[i][0], acc[i][1], acc[i][2], acc[i][3]);
            *(float4*)(dst + t * NU + n0 + (tn << 2)) = v;
        }
    }
}

// ---------------------------------------------------------------------------
// Fused tanh-score + softmax + context. One CTA = (b, 4 decoder rows).
// ae and en are SMEM-staged in 16KB double-buffered tiles via cp.async,
// removing the L2-latency dependence that bound rounds 1-3.
// ---------------------------------------------------------------------------
#define UT 32                       // u (or e) values per tile
#define TILE_HALFS (UT * 256)       // 8192 halfs = 16KB
#define NTILES (256 / UT)           // 8

__device__ __forceinline__ void stage_tile(unsigned sbase, const __half* g, int tid)
{
    unsigned s = sbase + tid * 16;
    const char* gp = (const char*)g + tid * 16;
#pragma unroll
    for (int i = 0; i < 4; i++)
        asm volatile("cp.async.cg.shared.global [%0], [%1], 16;\n"
                     :: "r"(s + i * 4096), "l"(gp + i * 4096) : "memory");
    asm volatile("cp.async.commit_group;" ::: "memory");
}

__global__ __launch_bounds__(256) void attn_kernel(const float* __restrict__ de,
                                                   const float* __restrict__ nu,
                                                   float* __restrict__ out)
{
    const int b   = blockIdx.x >> 6;          // 8 b * 64 groups
    const int t0  = (blockIdx.x & 63) << 2;   // 4 decoder rows per CTA
    const int tid = threadIdx.x;

    __shared__ __half buf[2][TILE_HALFS];     // 32KB double buffer
    __shared__ uint4  pk[256];                // {ad01, ad23, nu2, pad} per u
    __shared__ float4 alpha4[256];
    __shared__ float  red[8];

    const unsigned sb0 = (unsigned)__cvta_generic_to_shared(&buf[0][0]);
    const unsigned sb1 = (unsigned)__cvta_generic_to_shared(&buf[1][0]);
    const unsigned sbb[2] = {sb0, sb1};

    const __half* aeg = d_aeT_h + b * NU * NT;   // [u][e] tiles, contiguous
    const __half* eng = d_en_h  + b * NT * ND;   // [e][d] tiles, contiguous

    // prologue: stage ae tile 0; fill pk meanwhile
    stage_tile(sb0, aeg, tid);
    {
        const float* ap = d_ad + (b * NT + t0) * NU + tid;
        __half2 ad01 = __floats2half2_rn(ap[0],      ap[NU]);
        __half2 ad23 = __floats2half2_rn(ap[2 * NU], ap[3 * NU]);
        __half2 nu2  = __float2half2_rn(nu[tid]);
        uint4 p;
        p.x = *(unsigned*)&ad01;
        p.y = *(unsigned*)&ad23;
        p.z = *(unsigned*)&nu2;
        p.w = 0;
        pk[tid] = p;
    }

    // ---- scores: thread = e, tiles of 32 u from SMEM ----
    float m0 = 0.f, m1 = 0.f, m2 = 0.f, m3 = 0.f;
    for (int t = 0; t < NTILES; ++t) {
        if (t < NTILES - 1)
            stage_tile(sbb[(t + 1) & 1], aeg + (t + 1) * TILE_HALFS, tid);
        if (t < NTILES - 1)
            asm volatile("cp.async.wait_group 1;" ::: "memory");
        else
            asm volatile("cp.async.wait_group 0;" ::: "memory");
        __syncthreads();

        const __half* sa = &buf[t & 1][tid];
        const int u0 = t * UT;
#pragma unroll
        for (int c = 0; c < UT; c += 16) {      // 16-u chunks, fp16 acc
            __half2 a01 = __float2half2_rn(0.f);
            __half2 a23 = __float2half2_rn(0.f);
#pragma unroll
            for (int k = 0; k < 16; k++) {
                __half  a  = sa[(c + k) << 8];          // LDS.16, conflict-free
                uint4   p  = pk[u0 + c + k];            // LDS.128 broadcast
                __half2 ah = __half2half2(a);
                __half2 c01 = __hadd2(ah, *(__half2*)&p.x);
                __half2 c23 = __hadd2(ah, *(__half2*)&p.y);
                unsigned t01, t23;
                asm("tanh.approx.f16x2 %0, %1;" : "=r"(t01) : "r"(*(unsigned*)&c01));
                asm("tanh.approx.f16x2 %0, %1;" : "=r"(t23) : "r"(*(unsigned*)&c23));
                a01 = __hfma2(*(__half2*)&t01, *(__half2*)&p.z, a01);
                a23 = __hfma2(*(__half2*)&t23, *(__half2*)&p.z, a23);
            }
            float2 f01 = __half22float2(a01);
            float2 f23 = __half22float2(a23);
            m0 += f01.x; m1 += f01.y; m2 += f23.x; m3 += f23.y;
        }
        __syncthreads();
    }

    // prefetch en tile 0 — latency hides under the softmax math
    stage_tile(sb0, eng, tid);

    // ---- softmax over e for the 4 rows ----
    float mu[4] = {m0, m1, m2, m3};
    float al[4];
#pragma unroll
    for (int tt = 0; tt < 4; tt++) {
        float v  = mu[tt];
        float mx = v;
#pragma unroll
        for (int o = 16; o; o >>= 1) mx = fmaxf(mx, __shfl_xor_sync(0xffffffffu, mx, o));
        if ((tid & 31) == 0) red[tid >> 5] = mx;
        __syncthreads();
        mx = fmaxf(fmaxf(fmaxf(red[0], red[1]), fmaxf(red[2], red[3])),
                   fmaxf(fmaxf(red[4], red[5]), fmaxf(red[6], red[7])));
        __syncthreads();
        float ex = __expf(v - mx);
        float s  = ex;
#pragma unroll
        for (int o = 16; o; o >>= 1) s += __shfl_xor_sync(0xffffffffu, s, o);
        if ((tid & 31) == 0) red[tid >> 5] = s;
        __syncthreads();
        s = ((red[0] + red[1]) + (red[2] + red[3])) + ((red[4] + red[5]) + (red[6] + red[7]));
        __syncthreads();
        al[tt] = __fdividef(ex, s);
    }
    alpha4[tid] = make_float4(al[0], al[1], al[2], al[3]);
    __syncthreads();

    // ---- context: thread = d, tiles of 32 e from SMEM ----
    const float* dep = de + (b * NT + t0) * ND + tid;
    float o0 = dep[0], o1 = dep[ND], o2 = dep[2 * ND], o3 = dep[3 * ND];
    for (int t = 0; t < NTILES; ++t) {
        if (t < NTILES - 1)
            stage_tile(sbb[(t + 1) & 1], eng + (t + 1) * TILE_HALFS, tid);
        if (t < NTILES - 1)
            asm volatile("cp.async.wait_group 1;" ::: "memory");
        else
            asm volatile("cp.async.wait_group 0;" ::: "memory");
        __syncthreads();

        const __half* sv = &buf[t & 1][tid];
        const int e0 = t * UT;
#pragma unroll
        for (int k = 0; k < UT; k++) {
            float  v = __half2float(sv[k << 8]);   // LDS.16, conflict-free
            float4 a = alpha4[e0 + k];             // LDS.128 broadcast
            o0 = fmaf(a.x, v, o0);
            o1 = fmaf(a.y, v, o1);
            o2 = fmaf(a.z, v, o2);
            o3 = fmaf(a.w, v, o3);
        }
        __syncthreads();
    }
    float* op = out + (b * NT + t0) * ND + tid;
    op[0] = o0; op[ND] = o1; op[2 * ND] = o2; op[3 * ND] = o3;
}

extern "C" void kernel_launch(void* const* d_in, const int* in_sizes, int n_in,
                              void* d_out, int out_size)
{
    const float* en   = (const float*)d_in[0];   // (8,256,256)
    const float* de   = (const float*)d_in[1];   // (8,256,256)
    const float* w_en = (const float*)d_in[2];   // (256,256)
    const float* w_de = (const float*)d_in[3];   // (256,256)
    const float* nu   = (const float*)d_in[4];   // (256,1)
    float* out = (float*)d_out;                  // (8,256,256) fp32

    dim3 gg(4, 4, 16);
    gemm_kernel<<<gg, 256>>>(en, de, w_en, w_de);
    attn_kernel<<<NB * (NT / 4), 256>>>(de, nu, out);
}